// round 13
// baseline (speedup 1.0000x reference)
#include <cuda_runtime.h>
#include <cuda_fp16.h>
#include <math.h>
#include <stdint.h>

#define SEQ    2048
#define BATCH  2
#define DM     1024
#define NH     16
#define HD     64
#define DFF    4096
#define SB     (SEQ*BATCH)          /* 4096 rows */
#define LN_EPS 1e-5f

// ---------------- scratch (static __device__, allocation-rule safe) ---------
__device__ float g_att[SB*DM];
__device__ float g_x [SB*DM];

__device__ __half g_srch[SB*DM];
__device__ __half g_xh  [SB*DM];
__device__ __half g_ffh [SB*DFF];
__device__ __half g_qh  [SB*DM];
__device__ __half g_kh  [SB*DM];
__device__ __half g_vh  [SB*DM];
__device__ __half g_atth[SB*DM];
__device__ __half g_wqkvt[3*DM*DM];   // [3072][1024] pre-transposed
__device__ __half g_w1t [DFF*DM];
__device__ __half g_w2t [DM*DFF];
__device__ float2 g_rope[SEQ*32];     // cos/sin per (s, pair)

// ---------------- helpers ---------------------------------------------------
__device__ __forceinline__ unsigned pack_half2(float lo, float hi) {
    __half2 h = __floats2half2_rn(lo, hi);
    return reinterpret_cast<unsigned&>(h);
}
__device__ __forceinline__ void cp16(unsigned dst, const void* gmem) {
    asm volatile("cp.async.cg.shared.global [%0], [%1], 16;" :: "r"(dst), "l"(gmem));
}
__device__ __forceinline__ unsigned smem_u32(const void* p) {
    return (unsigned)__cvta_generic_to_shared(p);
}
__device__ __forceinline__ void mma_fp16(float c[4],
                                         unsigned a0, unsigned a1, unsigned a2, unsigned a3,
                                         unsigned b0, unsigned b1) {
    asm volatile(
        "mma.sync.aligned.m16n8k16.row.col.f32.f16.f16.f32 "
        "{%0,%1,%2,%3}, {%4,%5,%6,%7}, {%8,%9}, {%0,%1,%2,%3};"
        : "+f"(c[0]), "+f"(c[1]), "+f"(c[2]), "+f"(c[3])
        : "r"(a0), "r"(a1), "r"(a2), "r"(a3), "r"(b0), "r"(b1));
}
__device__ __forceinline__ void ldsm_x4(unsigned r[4], unsigned addr) {
    asm volatile("ldmatrix.sync.aligned.m8n8.x4.shared.b16 {%0,%1,%2,%3}, [%4];"
                 : "=r"(r[0]), "=r"(r[1]), "=r"(r[2]), "=r"(r[3]) : "r"(addr));
}
__device__ __forceinline__ void ldsm_x4_t(unsigned r[4], unsigned addr) {
    asm volatile("ldmatrix.sync.aligned.m8n8.x4.trans.shared.b16 {%0,%1,%2,%3}, [%4];"
                 : "=r"(r[0]), "=r"(r[1]), "=r"(r[2]), "=r"(r[3]) : "r"(addr));
}

// ================= GEMM mainloop core (128x128 tile, BK=64, 2-stage, occ 2) =
// 8 warps (4x2), warp tile 32x64. Dynamic smem: As/Bs [2][128][36] u32 (72 KB).
#define GEMM_SMEM (2 * 2 * 128 * 36 * 4)

#define GEMM_PROLOG(Aptr, Btptr, Kdim)                                           \
    extern __shared__ char dsm[];                                                \
    unsigned (*As)[128][36] = (unsigned(*)[128][36])dsm;                         \
    unsigned (*Bs)[128][36] = (unsigned(*)[128][36])(dsm + 2 * 128 * 36 * 4);    \
    const int tid  = threadIdx.x;                                                \
    const int warp = tid >> 5, lane = tid & 31;                                  \
    const int g = lane >> 2, t = lane & 3;                                       \
    const int wm = warp >> 1, wn = warp & 1;                                     \
    const int bm = blockIdx.y * 128, bn = blockIdx.x * 128;                      \
    float acc[2][8][4];                                                          \
    _Pragma("unroll") for (int i = 0; i < 2; i++)                                \
        _Pragma("unroll") for (int j = 0; j < 8; j++)                            \
            _Pragma("unroll") for (int r = 0; r < 4; r++) acc[i][j][r] = 0.f;    \
    const int NC = (Kdim) >> 6;                                                  \
    auto load_stage = [&](int s, int kt) {                                       \
        _Pragma("unroll")                                                        \
        for (int u = 0; u < 4; u++) {                                            \
            int f = tid + u * 256;                                               \
            int r = f >> 3, j = f & 7;                                           \
            cp16(smem_u32(&As[s][r][j * 4]), (Aptr)  + (size_t)(bm + r) * (Kdim) + kt + j * 8); \
            cp16(smem_u32(&Bs[s][r][j * 4]), (Btptr) + (size_t)(bn + r) * (Kdim) + kt + j * 8); \
        }                                                                        \
        asm volatile("cp.async.commit_group;");                                  \
    };                                                                           \
    load_stage(0, 0);                                                            \
    for (int c = 0; c < NC; c++) {                                               \
        if (c + 1 < NC) {                                                        \
            load_stage((c + 1) & 1, (c + 1) * 64);                               \
            asm volatile("cp.async.wait_group 1;");                              \
        } else {                                                                 \
            asm volatile("cp.async.wait_group 0;");                              \
        }                                                                        \
        __syncthreads();                                                         \
        const int s = c & 1;                                                     \
        _Pragma("unroll")                                                        \
        for (int ks = 0; ks < 4; ks++) {                                         \
            const int kp = ks * 8;                                               \
            unsigned a[2][4];                                                    \
            _Pragma("unroll")                                                    \
            for (int mf = 0; mf < 2; mf++) {                                     \
                int m = wm * 32 + mf * 16;                                       \
                ldsm_x4(a[mf], smem_u32(&As[s][m + (lane & 15)][kp + ((lane >> 4) << 2)])); \
            }                                                                    \
            _Pragma("unroll")                                                    \
            for (int np = 0; np < 4; np++) {                                     \
                int n = wn * 64 + np * 16;                                       \
                unsigned bf[4];                                                  \
                ldsm_x4(bf, smem_u32(&Bs[s][n + (lane & 7) + ((lane >> 4) << 3)][kp + (((lane >> 3) & 1) << 2)])); \
                mma_fp16(acc[0][np*2],   a[0][0], a[0][1], a[0][2], a[0][3], bf[0], bf[1]); \
                mma_fp16(acc[0][np*2+1], a[0][0], a[0][1], a[0][2], a[0][3], bf[2], bf[3]); \
                mma_fp16(acc[1][np*2],   a[1][0], a[1][1], a[1][2], a[1][3], bf[0], bf[1]); \
                mma_fp16(acc[1][np*2+1], a[1][0], a[1][1], a[1][2], a[1][3], bf[2], bf[3]); \
            }                                                                    \
        }                                                                        \
        __syncthreads();                                                         \
    }

// ---------------- generic GEMM (FFN): C = A@Bt^T + bias ---------------------
template<int RELU, int HALF_OUT>
__global__ __launch_bounds__(256, 2)
void gemm_fp16(const __half* __restrict__ A, const __half* __restrict__ Bt,
               const float* __restrict__ bias,
               float* __restrict__ Cf, __half* __restrict__ Ch,
               int M, int N, int K)
{
    GEMM_PROLOG(A, Bt, K)

    #pragma unroll
    for (int mf = 0; mf < 2; mf++) {
        int r0 = bm + wm * 32 + mf * 16 + g;
        #pragma unroll
        for (int nf = 0; nf < 8; nf++) {
            int col = bn + wn * 64 + nf * 8 + 2 * t;
            float2 bv = *(const float2*)(bias + col);
            float v0 = acc[mf][nf][0] + bv.x;
            float v1 = acc[mf][nf][1] + bv.y;
            float v2 = acc[mf][nf][2] + bv.x;
            float v3 = acc[mf][nf][3] + bv.y;
            if (RELU) {
                v0 = fmaxf(v0, 0.f); v1 = fmaxf(v1, 0.f);
                v2 = fmaxf(v2, 0.f); v3 = fmaxf(v3, 0.f);
            }
            if (HALF_OUT) {
                *(__half2*)(Ch + (size_t)r0       * N + col) = __floats2half2_rn(v0, v1);
                *(__half2*)(Ch + (size_t)(r0 + 8) * N + col) = __floats2half2_rn(v2, v3);
            } else {
                *(float2*)(Cf + (size_t)r0       * N + col) = make_float2(v0, v1);
                *(float2*)(Cf + (size_t)(r0 + 8) * N + col) = make_float2(v2, v3);
            }
        }
    }
}

// ---------------- fused QKV GEMM: rope(q,k) + fp16 stores -------------------
__global__ __launch_bounds__(256, 2)
void gemm_qkv(const __half* __restrict__ A, const __half* __restrict__ Bt,
              const float* __restrict__ q_b, const float* __restrict__ k_b,
              const float* __restrict__ v_b,
              const float2* __restrict__ tbl,
              __half* __restrict__ Qh, __half* __restrict__ Kh,
              __half* __restrict__ Vh)
{
    GEMM_PROLOG(A, Bt, DM)

    const int sec   = blockIdx.x >> 3;          // 0=q 1=k 2=v (8 blocks each)
    const int ncol0 = bn & 1023;
    const float* bias = sec == 0 ? q_b : (sec == 1 ? k_b : v_b);
    __half* outp      = sec == 0 ? Qh  : (sec == 1 ? Kh  : Vh);
    const bool dorope = sec < 2;

    #pragma unroll
    for (int mf = 0; mf < 2; mf++) {
        int r0 = bm + wm * 32 + mf * 16 + g;
        int s0 = r0 >> 1, s1 = (r0 + 8) >> 1;     // BATCH=2: seq pos
        #pragma unroll
        for (int nf = 0; nf < 8; nf++) {
            int col = ncol0 + wn * 64 + nf * 8 + 2 * t;
            float2 bv = *(const float2*)(bias + col);
            float v0 = acc[mf][nf][0] + bv.x;
            float v1 = acc[mf][nf][1] + bv.y;
            float v2 = acc[mf][nf][2] + bv.x;
            float v3 = acc[mf][nf][3] + bv.y;
            if (dorope) {
                int p = (col & 63) >> 1;
                float2 cs0 = tbl[s0 * 32 + p];
                float2 cs1 = tbl[s1 * 32 + p];
                float t0 = v0 * cs0.x - v1 * cs0.y;
                v1 = v1 * cs0.x + v0 * cs0.y; v0 = t0;
                float t2 = v2 * cs1.x - v3 * cs1.y;
                v3 = v3 * cs1.x + v2 * cs1.y; v2 = t2;
            }
            *(__half2*)(outp + (size_t)r0       * DM + col) = __floats2half2_rn(v0, v1);
            *(__half2*)(outp + (size_t)(r0 + 8) * DM + col) = __floats2half2_rn(v2, v3);
        }
    }
}

// ---------------- merged pre-pass: one launch, block-range partitioned ------
// [0,4096)           : src f32 -> fp16 (1 float4/thread)
// [4096,7168)        : qkv weight transpose+convert (z = (b-4096)/1024)
// [7168,11264)       : w1 transpose  (K=DM,  N=DFF)
// [11264,15360)      : w2 transpose  (K=DFF, N=DM)
// [15360,15616)      : rope cos/sin table
#define PREPASS_BLOCKS 15616
__global__ void prepass(const float* __restrict__ src,
                        const float* __restrict__ q_w, const float* __restrict__ k_w,
                        const float* __restrict__ v_w,
                        const float* __restrict__ w1,  const float* __restrict__ w2,
                        __half* __restrict__ sh, __half* __restrict__ wqkvt,
                        __half* __restrict__ w1t, __half* __restrict__ w2t,
                        float2* __restrict__ tbl)
{
    __shared__ float tl[32][33];
    const int tid = threadIdx.x;
    int b = blockIdx.x;

    if (b < 4096) {                       // to_half(src)
        int i = b * 256 + tid;
        float4 v = *(const float4*)(src + (size_t)i * 4);
        *(__half2*)(sh + (size_t)i * 4)     = __floats2half2_rn(v.x, v.y);
        *(__half2*)(sh + (size_t)i * 4 + 2) = __floats2half2_rn(v.z, v.w);
        return;
    }
    b -= 4096;
    const float* W; __half* T; int K, N;
    if (b < 3072) {                       // qkv transposes
        int z = b / 1024;
        W = z == 0 ? q_w : (z == 1 ? k_w : v_w);
        T = wqkvt + (size_t)z * DM * DM;
        K = DM; N = DM;
        b = b % 1024;
    } else if (b < 3072 + 4096) {         // w1
        b -= 3072; W = w1; T = w1t; K = DM; N = DFF;
    } else if (b < 3072 + 8192) {         // w2
        b -= 3072 + 4096; W = w2; T = w2t; K = DFF; N = DM;
    } else {                              // rope table
        int i = (b - (3072 + 8192)) * 256 + tid;
        int s = i >> 5, p = i & 31;
        float ang = (float)s * powf(10000.0f, -(float)p / 32.0f);
        tbl[i] = make_float2(cosf(ang), sinf(ang));
        return;
    }
    const int nb = N / 32;
    const int n0 = (b % nb) * 32, k0 = (b / nb) * 32;
    const int x = tid & 31, y = tid >> 5;
    #pragma unroll
    for (int i = 0; i < 4; i++) {
        int r = y + i * 8;
        tl[r][x] = W[(size_t)(k0 + r) * N + n0 + x];
    }
    __syncthreads();
    #pragma unroll
    for (int i = 0; i < 4; i++) {
        int r = y + i * 8;
        T[(size_t)(n0 + r) * K + k0 + x] = __float2half_rn(tl[x][r]);
    }
}

// ---------------- tensor-core flash attention (cp.async dbl-buf, fp16 out) --
// Grid (SEQ/128, NH, BATCH), 256 thr = 8 warps, warp owns 16 q-rows.
__global__ __launch_bounds__(256)
void attn_mma(const __half* __restrict__ Q, const __half* __restrict__ K,
              const __half* __restrict__ V, __half* __restrict__ O)
{
    const int qt = blockIdx.x, h = blockIdx.y, b = blockIdx.z;
    const int stride = BATCH * DM;
    const size_t base = (size_t)b * DM + h * HD;
    const int tid = threadIdx.x;
    const int w = tid >> 5, lane = tid & 31;
    const int g = lane >> 2, t = lane & 3;
    const int qrow0 = qt * 128 + w * 16 + g;

    __shared__ unsigned Ks[2][64][36];   // u32 view of fp16 [64][72-pad]
    __shared__ __half   Vs[2][64][72];   // fp16 rows (64 data + 8 pad)

    auto load_tile = [&](int s, int kt) {
        const __half* Kg = K + (size_t)kt * stride + base;
        const __half* Vg = V + (size_t)kt * stride + base;
        #pragma unroll
        for (int u = 0; u < 2; u++) {
            int i = tid + u * 256;
            int r = i >> 3, j = i & 7;
            cp16(smem_u32(&Ks[s][r][j * 4]), Kg + (size_t)r * stride + j * 8);
            cp16(smem_u32(&Vs[s][r][j * 8]), Vg + (size_t)r * stride + j * 8);
        }
        asm volatile("cp.async.commit_group;");
    };

    // Q fragments straight from fp16 gmem
    unsigned qf[4][4];
    {
        const __half* Qr0 = Q + (size_t)qrow0 * stride + base;
        const __half* Qr1 = Qr0 + (size_t)8 * stride;
        #pragma unroll
        for (int c = 0; c < 4; c++) {
            qf[c][0] = *(const unsigned*)(Qr0 + 16*c + 2*t);
            qf[c][1] = *(const unsigned*)(Qr1 + 16*c + 2*t);
            qf[c][2] = *(const unsigned*)(Qr0 + 16*c + 8 + 2*t);
            qf[c][3] = *(const unsigned*)(Qr1 + 16*c + 8 + 2*t);
        }
    }

    float oacc[8][4];
    #pragma unroll
    for (int n = 0; n < 8; n++)
        #pragma unroll
        for (int r = 0; r < 4; r++) oacc[n][r] = 0.f;
    float m0 = -1e30f, m1 = -1e30f, l0 = 0.f, l1 = 0.f;

    load_tile(0, 0);

    const int NT = SEQ / 64;
    for (int it = 0; it < NT; it++) {
        if (it + 1 < NT) {
            load_tile((it + 1) & 1, (it + 1) * 64);
            asm volatile("cp.async.wait_group 1;");
        } else {
            asm volatile("cp.async.wait_group 0;");
        }
        __syncthreads();
        const int s = it & 1;

        // ---- S = Q @ K^T ----
        float sacc[8][4];
        #pragma unroll
        for (int n = 0; n < 8; n++)
            #pragma unroll
            for (int r = 0; r < 4; r++) sacc[n][r] = 0.f;

        #pragma unroll
        for (int c = 0; c < 4; c++) {
            #pragma unroll
            for (int np = 0; np < 4; np++) {
                unsigned kf[4];
                ldsm_x4(kf, smem_u32(&Ks[s][np*16 + (lane & 7) + ((lane >> 4) << 3)]
                                        [c*8 + (((lane >> 3) & 1) << 2)]));
                mma_fp16(sacc[np*2],   qf[c][0], qf[c][1], qf[c][2], qf[c][3], kf[0], kf[1]);
                mma_fp16(sacc[np*2+1], qf[c][0], qf[c][1], qf[c][2], qf[c][3], kf[2], kf[3]);
            }
        }

        // ---- online softmax ----
        float mx0 = -1e30f, mx1 = -1e30f;
        #pragma unroll
        for (int n = 0; n < 8; n++) {
            sacc[n][0] *= 0.125f; sacc[n][1] *= 0.125f;
            sacc[n][2] *= 0.125f; sacc[n][3] *= 0.125f;
            mx0 = fmaxf(mx0, fmaxf(sacc[n][0], sacc[n][1]));
            mx1 = fmaxf(mx1, fmaxf(sacc[n][2], sacc[n][3]));
        }
        mx0 = fmaxf(mx0, __shfl_xor_sync(0xFFFFFFFFu, mx0, 1));
        mx0 = fmaxf(mx0, __shfl_xor_sync(0xFFFFFFFFu, mx0, 2));
        mx1 = fmaxf(mx1, __shfl_xor_sync(0xFFFFFFFFu, mx1, 1));
        mx1 = fmaxf(mx1, __shfl_xor_sync(0xFFFFFFFFu, mx1, 2));

        float nm0 = fmaxf(m0, mx0), nm1 = fmaxf(m1, mx1);
        float sc0 = __expf(m0 - nm0), sc1 = __expf(m1 - nm1);
        m0 = nm0; m1 = nm1;

        float rs0 = 0.f, rs1 = 0.f;
        unsigned pa[4][4];
        #pragma unroll
        for (int n = 0; n < 8; n++) {
            float p0 = __expf(sacc[n][0] - nm0);
            float p1 = __expf(sacc[n][1] - nm0);
            float p2 = __expf(sacc[n][2] - nm1);
            float p3 = __expf(sacc[n][3] - nm1);
            rs0 += p0 + p1; rs1 += p2 + p3;
            int kk = n >> 1, half = n & 1;
            pa[kk][half*2 + 0] = pack_half2(p0, p1);
            pa[kk][half*2 + 1] = pack_half2(p2, p3);
        }
        rs0 += __shfl_xor_sync(0xFFFFFFFFu, rs0, 1);
        rs0 += __shfl_xor_sync(0xFFFFFFFFu, rs0, 2);
        rs1 += __shfl_xor_sync(0xFFFFFFFFu, rs1, 1);
        rs1 += __shfl_xor_sync(0xFFFFFFFFu, rs1, 2);
        l0 = l0 * sc0 + rs0;
        l1 = l1 * sc1 + rs1;

        #pragma unroll
        for (int n = 0; n < 8; n++) {
            oacc[n][0] *= sc0; oacc[n][1] *= sc0;
            oacc[n][2] *= sc1; oacc[n][3] *= sc1;
        }

        // ---- O += P @ V (V frags via ldmatrix.trans) ----
        #pragma unroll
        for (int kk = 0; kk < 4; kk++) {
            #pragma unroll
            for (int nn = 0; nn < 8; nn += 2) {
                unsigned vf[4];
                ldsm_x4_t(vf, smem_u32(&Vs[s][kk*16 + (lane & 15)][(nn + (lane >> 4)) * 8]));
                mma_fp16(oacc[nn],   pa[kk][0], pa[kk][1], pa[kk][2], pa[kk][3], vf[0], vf[1]);
                mma_fp16(oacc[nn+1], pa[kk][0], pa[kk][1], pa[kk][2], pa[kk][3], vf[2], vf[3]);
            }
        }
        __syncthreads();
    }

    float inv0 = 1.f / l0, inv1 = 1.f / l1;
    __half* Or0 = O + (size_t)qrow0 * stride + base;
    __half* Or1 = Or0 + (size_t)8 * stride;
    #pragma unroll
    for (int nn = 0; nn < 8; nn++) {
        *(__half2*)(Or0 + nn*8 + 2*t) =
            __floats2half2_rn(oacc[nn][0] * inv0, oacc[nn][1] * inv0);
        *(__half2*)(Or1 + nn*8 + 2*t) =
            __floats2half2_rn(oacc[nn][2] * inv1, oacc[nn][3] * inv1);
    }
}

// ---------------- residual add + LN, fp16 B operand (LN1) -------------------
__global__ __launch_bounds__(256)
void add_ln_hB(const float* __restrict__ A, const __half* __restrict__ B,
               const float* __restrict__ g, const float* __restrict__ bta,
               float* __restrict__ out, __half* __restrict__ oh)
{
    const int row = blockIdx.x;
    const int tid = threadIdx.x;
    const float* a = A + (size_t)row * DM;
    const __half* b = B + (size_t)row * DM;

    float v[4];
    float4 va = *(const float4*)(a + tid * 4);
    __half2 hb0 = *(const __half2*)(b + tid * 4);
    __half2 hb1 = *(const __half2*)(b + tid * 4 + 2);
    float2 fb0 = __half22float2(hb0);
    float2 fb1 = __half22float2(hb1);
    v[0] = va.x + fb0.x; v[1] = va.y + fb0.y;
    v[2] = va.z + fb1.x; v[3] = va.w + fb1.y;

    float sum = v[0] + v[1] + v[2] + v[3];
    float sq  = v[0]*v[0] + v[1]*v[1] + v[2]*v[2] + v[3]*v[3];

    #pragma unroll
    for (int off = 16; off; off >>= 1) {
        sum += __shfl_xor_sync(0xFFFFFFFF, sum, off);
        sq  += __shfl_xor_sync(0xFFFFFFFF, sq,  off);
    }
    __shared__ float ssum[8], ssq[8], sstat[2];
    if ((tid & 31) == 0) { ssum[tid >> 5] = sum; ssq[tid >> 5] = sq; }
    __syncthreads();
    if (tid == 0) {
        float ts = 0.f, tq = 0.f;
        #pragma unroll
        for (int i = 0; i < 8; i++) { ts += ssum[i]; tq += ssq[i]; }
        float mean = ts / (float)DM;
        float var  = tq / (float)DM - mean * mean;
        sstat[0] = mean;
        sstat[1] = rsqrtf(fmaxf(var, 0.f) + LN_EPS);
    }
    __syncthreads();
    float mean = sstat[0], inv = sstat[1];

    float4 vg = *(const float4*)(g   + tid * 4);
    float4 vB = *(const float4*)(bta + tid * 4);
    float4 r;
    r.x = (v[0] - mean) * inv * vg.x + vB.x;
    r.y = (v[1] - mean) * inv * vg.y + vB.y;
    r.z = (v[2] - mean) * inv * vg.z + vB.z;
    r.w = (v[3] - mean) * inv * vg.w + vB.w;
    *(float4*)(out + (size_t)row * DM + tid * 4) = r;

    *(__half2*)(oh + (size_t)row * DM + tid * 4)     = __floats2half2_rn(r.x, r.y);
    *(__half2*)(oh + (size_t)row * DM + tid * 4 + 2) = __floats2half2_rn(r.z, r.w);
}

// ---------------- residual add + LN, fp32 B operand (LN2) -------------------
__global__ __launch_bounds__(256)
void add_ln_kernel(const float* __restrict__ A, const float* __restrict__ B,
                   const float* __restrict__ g, const float* __restrict__ bta,
                   float* __restrict__ out)
{
    const int row = blockIdx.x;
    const int tid = threadIdx.x;
    const float* a = A + (size_t)row * DM;
    const float* b = B + (size_t)row * DM;

    float v[4];
    float4 va = *(const float4*)(a + tid * 4);
    float4 vb = *(const float4*)(b + tid * 4);
    v[0] = va.x + vb.x; v[1] = va.y + vb.y;
    v[2] = va.z + vb.z; v[3] = va.w + vb.w;

    float sum = v[0] + v[1] + v[2] + v[3];
    float sq  = v[0]*v[0] + v[1]*v[1] + v[2]*v[2] + v[3]*v[3];

    #pragma unroll
    for (int off = 16; off; off >>= 1) {
        sum += __shfl_xor_sync(0xFFFFFFFF, sum, off);
        sq  += __shfl_xor_sync(0xFFFFFFFF, sq,  off);
    }
    __shared__ float ssum[8], ssq[8], sstat[2];
    if ((tid & 31) == 0) { ssum[tid >> 5] = sum; ssq[tid >> 5] = sq; }
    __syncthreads();
    if (tid == 0) {
        float ts = 0.f, tq = 0.f;
        #pragma unroll
        for (int i = 0; i < 8; i++) { ts += ssum[i]; tq += ssq[i]; }
        float mean = ts / (float)DM;
        float var  = tq / (float)DM - mean * mean;
        sstat[0] = mean;
        sstat[1] = rsqrtf(fmaxf(var, 0.f) + LN_EPS);
    }
    __syncthreads();
    float mean = sstat[0], inv = sstat[1];

    float4 vg = *(const float4*)(g   + tid * 4);
    float4 vB = *(const float4*)(bta + tid * 4);
    float4 r;
    r.x = (v[0] - mean) * inv * vg.x + vB.x;
    r.y = (v[1] - mean) * inv * vg.y + vB.y;
    r.z = (v[2] - mean) * inv * vg.z + vB.z;
    r.w = (v[3] - mean) * inv * vg.w + vB.w;
    *(float4*)(out + (size_t)row * DM + tid * 4) = r;
}

// ---------------------------------------------------------------------------
extern "C" void kernel_launch(void* const* d_in, const int* in_sizes, int n_in,
                              void* d_out, int out_size)
{
    const float* src  = (const float*)d_in[0];
    const float* q_w  = (const float*)d_in[1];
    const float* q_b  = (const float*)d_in[2];
    const float* k_w  = (const float*)d_in[3];
    const float* k_b  = (const float*)d_in[4];
    const float* v_w  = (const float*)d_in[5];
    const float* v_b  = (const float*)d_in[6];
    const float* w1   = (const float*)d_in[7];
    const float* b1   = (const float*)d_in[8];
    const float* w2   = (const float*)d_in[9];
    const float* b2   = (const float*)d_in[10];
    const float* ln1g = (const float*)d_in[11];
    const float* ln1b = (const float*)d_in[12];
    const float* ln2g = (const float*)d_in[13];
    const float* ln2b = (const float*)d_in[14];
    float* out = (float*)d_out;

    float *att, *x;
    float2* tbl;
    __half *sh, *xh, *ffh, *qh, *kh, *vh, *atth, *wqkvt, *w1t, *w2t;
    cudaGetSymbolAddress((void**)&att,   g_att);
    cudaGetSymbolAddress((void**)&x,     g_x);
    cudaGetSymbolAddress((void**)&sh,    g_srch);
    cudaGetSymbolAddress((void**)&xh,    g_xh);
    cudaGetSymbolAddress((void**)&ffh,   g_ffh);
    cudaGetSymbolAddress((void**)&qh,    g_qh);
    cudaGetSymbolAddress((void**)&kh,    g_kh);
    cudaGetSymbolAddress((void**)&vh,    g_vh);
    cudaGetSymbolAddress((void**)&atth,  g_atth);
    cudaGetSymbolAddress((void**)&wqkvt, g_wqkvt);
    cudaGetSymbolAddress((void**)&w1t,   g_w1t);
    cudaGetSymbolAddress((void**)&w2t,   g_w2t);
    cudaGetSymbolAddress((void**)&tbl,   g_rope);

    cudaFuncSetAttribute(gemm_qkv, cudaFuncAttributeMaxDynamicSharedMemorySize, GEMM_SMEM);
    cudaFuncSetAttribute(gemm_fp16<1,1>, cudaFuncAttributeMaxDynamicSharedMemorySize, GEMM_SMEM);
    cudaFuncSetAttribute(gemm_fp16<0,0>, cudaFuncAttributeMaxDynamicSharedMemorySize, GEMM_SMEM);

    // merged pre-pass: src->fp16, 5 weight transposes, rope table (one launch)
    prepass<<<PREPASS_BLOCKS, 256>>>(src, q_w, k_w, v_w, w1, w2,
                                     sh, wqkvt, w1t, w2t, tbl);

    // fused QKV (+bias +rope) -> fp16 q,k,v
    gemm_qkv<<<dim3(3 * DM / 128, SB / 128), 256, GEMM_SMEM>>>(
        sh, wqkvt, q_b, k_b, v_b, tbl, qh, kh, vh);

    attn_mma<<<dim3(SEQ / 128, NH, BATCH), 256>>>(qh, kh, vh, atth);
    add_ln_hB<<<SB, 256>>>(src, atth, ln1g, ln1b, x, xh);

    // FFN
    gemm_fp16<1,1><<<dim3(DFF / 128, SB / 128), 256, GEMM_SMEM>>>(
        xh, w1t, b1, nullptr, ffh, SB, DFF, DM);
    gemm_fp16<0,0><<<dim3(DM / 128, SB / 128), 256, GEMM_SMEM>>>(
        ffh, w2t, b2, att, nullptr, SB, DM, DFF);

    add_ln_kernel<<<SB, 256>>>(x, att, ln2g, ln2b, out);
}

// round 14
// speedup vs baseline: 1.4988x; 1.4988x over previous
#include <cuda_runtime.h>
#include <cuda_fp16.h>
#include <math.h>
#include <stdint.h>

#define SEQ    2048
#define BATCH  2
#define DM     1024
#define NH     16
#define HD     64
#define DFF    4096
#define SB     (SEQ*BATCH)          /* 4096 rows */
#define LN_EPS 1e-5f

// ---------------- scratch (static __device__, allocation-rule safe) ---------
__device__ float g_att[SB*DM];
__device__ float g_x [SB*DM];

__device__ __half g_srch[SB*DM];
__device__ __half g_xh  [SB*DM];
__device__ __half g_ffh [SB*DFF];
__device__ __half g_qh  [SB*DM];
__device__ __half g_kh  [SB*DM];
__device__ __half g_vh  [SB*DM];
__device__ __half g_atth[SB*DM];
__device__ __half g_wqkvt[3*DM*DM];   // [3072][1024] pre-transposed
__device__ __half g_w1t [DFF*DM];
__device__ __half g_w2t [DM*DFF];
__device__ float2 g_rope[SEQ*32];     // cos/sin per (s, pair)

// ---------------- helpers ---------------------------------------------------
__device__ __forceinline__ unsigned pack_half2(float lo, float hi) {
    __half2 h = __floats2half2_rn(lo, hi);
    return reinterpret_cast<unsigned&>(h);
}
__device__ __forceinline__ void cp16(unsigned dst, const void* gmem) {
    asm volatile("cp.async.cg.shared.global [%0], [%1], 16;" :: "r"(dst), "l"(gmem));
}
__device__ __forceinline__ unsigned smem_u32(const void* p) {
    return (unsigned)__cvta_generic_to_shared(p);
}
__device__ __forceinline__ void mma_fp16(float c[4],
                                         unsigned a0, unsigned a1, unsigned a2, unsigned a3,
                                         unsigned b0, unsigned b1) {
    asm volatile(
        "mma.sync.aligned.m16n8k16.row.col.f32.f16.f16.f32 "
        "{%0,%1,%2,%3}, {%4,%5,%6,%7}, {%8,%9}, {%0,%1,%2,%3};"
        : "+f"(c[0]), "+f"(c[1]), "+f"(c[2]), "+f"(c[3])
        : "r"(a0), "r"(a1), "r"(a2), "r"(a3), "r"(b0), "r"(b1));
}
__device__ __forceinline__ void ldsm_x4(unsigned r[4], unsigned addr) {
    asm volatile("ldmatrix.sync.aligned.m8n8.x4.shared.b16 {%0,%1,%2,%3}, [%4];"
                 : "=r"(r[0]), "=r"(r[1]), "=r"(r[2]), "=r"(r[3]) : "r"(addr));
}
__device__ __forceinline__ void ldsm_x4_t(unsigned r[4], unsigned addr) {
    asm volatile("ldmatrix.sync.aligned.m8n8.x4.trans.shared.b16 {%0,%1,%2,%3}, [%4];"
                 : "=r"(r[0]), "=r"(r[1]), "=r"(r[2]), "=r"(r[3]) : "r"(addr));
}

// ================= GEMM mainloop core (128x128 tile, BK=64, 2-stage, occ 2) =
// 8 warps (4x2), warp tile 32x64. Dynamic smem: As/Bs [2][128][36] u32 (72 KB).
#define GEMM_SMEM (2 * 2 * 128 * 36 * 4)

#define GEMM_PROLOG(Aptr, Btptr, Kdim)                                           \
    extern __shared__ char dsm[];                                                \
    unsigned (*As)[128][36] = (unsigned(*)[128][36])dsm;                         \
    unsigned (*Bs)[128][36] = (unsigned(*)[128][36])(dsm + 2 * 128 * 36 * 4);    \
    const int tid  = threadIdx.x;                                                \
    const int warp = tid >> 5, lane = tid & 31;                                  \
    const int g = lane >> 2, t = lane & 3;                                       \
    const int wm = warp >> 1, wn = warp & 1;                                     \
    const int bm = blockIdx.y * 128, bn = blockIdx.x * 128;                      \
    float acc[2][8][4];                                                          \
    _Pragma("unroll") for (int i = 0; i < 2; i++)                                \
        _Pragma("unroll") for (int j = 0; j < 8; j++)                            \
            _Pragma("unroll") for (int r = 0; r < 4; r++) acc[i][j][r] = 0.f;    \
    const int NC = (Kdim) >> 6;                                                  \
    auto load_stage = [&](int s, int kt) {                                       \
        _Pragma("unroll")                                                        \
        for (int u = 0; u < 4; u++) {                                            \
            int f = tid + u * 256;                                               \
            int r = f >> 3, j = f & 7;                                           \
            cp16(smem_u32(&As[s][r][j * 4]), (Aptr)  + (size_t)(bm + r) * (Kdim) + kt + j * 8); \
            cp16(smem_u32(&Bs[s][r][j * 4]), (Btptr) + (size_t)(bn + r) * (Kdim) + kt + j * 8); \
        }                                                                        \
        asm volatile("cp.async.commit_group;");                                  \
    };                                                                           \
    load_stage(0, 0);                                                            \
    for (int c = 0; c < NC; c++) {                                               \
        if (c + 1 < NC) {                                                        \
            load_stage((c + 1) & 1, (c + 1) * 64);                               \
            asm volatile("cp.async.wait_group 1;");                              \
        } else {                                                                 \
            asm volatile("cp.async.wait_group 0;");                              \
        }                                                                        \
        __syncthreads();                                                         \
        const int s = c & 1;                                                     \
        _Pragma("unroll")                                                        \
        for (int ks = 0; ks < 4; ks++) {                                         \
            const int kp = ks * 8;                                               \
            unsigned a[2][4];                                                    \
            _Pragma("unroll")                                                    \
            for (int mf = 0; mf < 2; mf++) {                                     \
                int m = wm * 32 + mf * 16;                                       \
                ldsm_x4(a[mf], smem_u32(&As[s][m + (lane & 15)][kp + ((lane >> 4) << 2)])); \
            }                                                                    \
            _Pragma("unroll")                                                    \
            for (int np = 0; np < 4; np++) {                                     \
                int n = wn * 64 + np * 16;                                       \
                unsigned bf[4];                                                  \
                ldsm_x4(bf, smem_u32(&Bs[s][n + (lane & 7) + ((lane >> 4) << 3)][kp + (((lane >> 3) & 1) << 2)])); \
                mma_fp16(acc[0][np*2],   a[0][0], a[0][1], a[0][2], a[0][3], bf[0], bf[1]); \
                mma_fp16(acc[0][np*2+1], a[0][0], a[0][1], a[0][2], a[0][3], bf[2], bf[3]); \
                mma_fp16(acc[1][np*2],   a[1][0], a[1][1], a[1][2], a[1][3], bf[0], bf[1]); \
                mma_fp16(acc[1][np*2+1], a[1][0], a[1][1], a[1][2], a[1][3], bf[2], bf[3]); \
            }                                                                    \
        }                                                                        \
        __syncthreads();                                                         \
    }

// ---------------- generic GEMM (FFN): C = A@Bt^T + bias ---------------------
template<int RELU, int HALF_OUT>
__global__ __launch_bounds__(256, 2)
void gemm_fp16(const __half* __restrict__ A, const __half* __restrict__ Bt,
               const float* __restrict__ bias,
               float* __restrict__ Cf, __half* __restrict__ Ch,
               int M, int N, int K)
{
    GEMM_PROLOG(A, Bt, K)

    #pragma unroll
    for (int mf = 0; mf < 2; mf++) {
        int r0 = bm + wm * 32 + mf * 16 + g;
        #pragma unroll
        for (int nf = 0; nf < 8; nf++) {
            int col = bn + wn * 64 + nf * 8 + 2 * t;
            float2 bv = *(const float2*)(bias + col);
            float v0 = acc[mf][nf][0] + bv.x;
            float v1 = acc[mf][nf][1] + bv.y;
            float v2 = acc[mf][nf][2] + bv.x;
            float v3 = acc[mf][nf][3] + bv.y;
            if (RELU) {
                v0 = fmaxf(v0, 0.f); v1 = fmaxf(v1, 0.f);
                v2 = fmaxf(v2, 0.f); v3 = fmaxf(v3, 0.f);
            }
            if (HALF_OUT) {
                *(__half2*)(Ch + (size_t)r0       * N + col) = __floats2half2_rn(v0, v1);
                *(__half2*)(Ch + (size_t)(r0 + 8) * N + col) = __floats2half2_rn(v2, v3);
            } else {
                *(float2*)(Cf + (size_t)r0       * N + col) = make_float2(v0, v1);
                *(float2*)(Cf + (size_t)(r0 + 8) * N + col) = make_float2(v2, v3);
            }
        }
    }
}

// ---------------- fused QKV GEMM: rope(q,k) + fp16 stores -------------------
__global__ __launch_bounds__(256, 2)
void gemm_qkv(const __half* __restrict__ A, const __half* __restrict__ Bt,
              const float* __restrict__ q_b, const float* __restrict__ k_b,
              const float* __restrict__ v_b,
              const float2* __restrict__ tbl,
              __half* __restrict__ Qh, __half* __restrict__ Kh,
              __half* __restrict__ Vh)
{
    GEMM_PROLOG(A, Bt, DM)

    const int sec   = blockIdx.x >> 3;          // 0=q 1=k 2=v (8 blocks each)
    const int ncol0 = bn & 1023;
    const float* bias = sec == 0 ? q_b : (sec == 1 ? k_b : v_b);
    __half* outp      = sec == 0 ? Qh  : (sec == 1 ? Kh  : Vh);
    const bool dorope = sec < 2;

    #pragma unroll
    for (int mf = 0; mf < 2; mf++) {
        int r0 = bm + wm * 32 + mf * 16 + g;
        int s0 = r0 >> 1, s1 = (r0 + 8) >> 1;     // BATCH=2: seq pos
        #pragma unroll
        for (int nf = 0; nf < 8; nf++) {
            int col = ncol0 + wn * 64 + nf * 8 + 2 * t;
            float2 bv = *(const float2*)(bias + col);
            float v0 = acc[mf][nf][0] + bv.x;
            float v1 = acc[mf][nf][1] + bv.y;
            float v2 = acc[mf][nf][2] + bv.x;
            float v3 = acc[mf][nf][3] + bv.y;
            if (dorope) {
                int p = (col & 63) >> 1;
                float2 cs0 = tbl[s0 * 32 + p];
                float2 cs1 = tbl[s1 * 32 + p];
                float t0 = v0 * cs0.x - v1 * cs0.y;
                v1 = v1 * cs0.x + v0 * cs0.y; v0 = t0;
                float t2 = v2 * cs1.x - v3 * cs1.y;
                v3 = v3 * cs1.x + v2 * cs1.y; v2 = t2;
            }
            *(__half2*)(outp + (size_t)r0       * DM + col) = __floats2half2_rn(v0, v1);
            *(__half2*)(outp + (size_t)(r0 + 8) * DM + col) = __floats2half2_rn(v2, v3);
        }
    }
}

// ---------------- pre-pass kernels (round-12 proven set) --------------------
__global__ void to_half(const float* __restrict__ X, __half* __restrict__ H, int n4)
{
    int i = blockIdx.x * blockDim.x + threadIdx.x;
    if (i >= n4) return;
    float4 v = *(const float4*)(X + i * 4);
    *(__half2*)(H + i * 4)     = __floats2half2_rn(v.x, v.y);
    *(__half2*)(H + i * 4 + 2) = __floats2half2_rn(v.z, v.w);
}

__global__ void transpose_half(const float* __restrict__ W, __half* __restrict__ T,
                               int K, int N)
{
    __shared__ float tl[32][33];
    int n0 = blockIdx.x * 32, k0 = blockIdx.y * 32;
    int x = threadIdx.x, y = threadIdx.y;
    #pragma unroll
    for (int i = 0; i < 4; i++) {
        int r = y + i * 8;
        tl[r][x] = W[(size_t)(k0 + r) * N + n0 + x];
    }
    __syncthreads();
    #pragma unroll
    for (int i = 0; i < 4; i++) {
        int r = y + i * 8;
        T[(size_t)(n0 + r) * K + k0 + x] = __float2half_rn(tl[x][r]);
    }
}

// all three QKV weights in one launch (z selects the weight)
__global__ void transpose_qkv(const float* __restrict__ Wq, const float* __restrict__ Wk,
                              const float* __restrict__ Wv, __half* __restrict__ T)
{
    __shared__ float tl[32][33];
    const float* W = blockIdx.z == 0 ? Wq : (blockIdx.z == 1 ? Wk : Wv);
    __half* Tz = T + (size_t)blockIdx.z * DM * DM;
    int n0 = blockIdx.x * 32, k0 = blockIdx.y * 32;
    int x = threadIdx.x, y = threadIdx.y;
    #pragma unroll
    for (int i = 0; i < 4; i++) {
        int r = y + i * 8;
        tl[r][x] = W[(size_t)(k0 + r) * DM + n0 + x];
    }
    __syncthreads();
    #pragma unroll
    for (int i = 0; i < 4; i++) {
        int r = y + i * 8;
        Tz[(size_t)(n0 + r) * DM + k0 + x] = __float2half_rn(tl[x][r]);
    }
}

__global__ void rope_table(float2* __restrict__ tbl)
{
    int i = blockIdx.x * blockDim.x + threadIdx.x;
    if (i >= SEQ * 32) return;
    int s = i >> 5, p = i & 31;
    float ang = (float)s * powf(10000.0f, -(float)p / 32.0f);
    tbl[i] = make_float2(cosf(ang), sinf(ang));
}

// ---------------- tensor-core flash attention (cp.async dbl-buf, fp16 out) --
// Grid (SEQ/128, NH, BATCH), 256 thr = 8 warps, warp owns 16 q-rows.
__global__ __launch_bounds__(256)
void attn_mma(const __half* __restrict__ Q, const __half* __restrict__ K,
              const __half* __restrict__ V, __half* __restrict__ O)
{
    const int qt = blockIdx.x, h = blockIdx.y, b = blockIdx.z;
    const int stride = BATCH * DM;
    const size_t base = (size_t)b * DM + h * HD;
    const int tid = threadIdx.x;
    const int w = tid >> 5, lane = tid & 31;
    const int g = lane >> 2, t = lane & 3;
    const int qrow0 = qt * 128 + w * 16 + g;

    __shared__ unsigned Ks[2][64][36];   // u32 view of fp16 [64][72-pad]
    __shared__ __half   Vs[2][64][72];   // fp16 rows (64 data + 8 pad)

    auto load_tile = [&](int s, int kt) {
        const __half* Kg = K + (size_t)kt * stride + base;
        const __half* Vg = V + (size_t)kt * stride + base;
        #pragma unroll
        for (int u = 0; u < 2; u++) {
            int i = tid + u * 256;
            int r = i >> 3, j = i & 7;
            cp16(smem_u32(&Ks[s][r][j * 4]), Kg + (size_t)r * stride + j * 8);
            cp16(smem_u32(&Vs[s][r][j * 8]), Vg + (size_t)r * stride + j * 8);
        }
        asm volatile("cp.async.commit_group;");
    };

    // Q fragments straight from fp16 gmem
    unsigned qf[4][4];
    {
        const __half* Qr0 = Q + (size_t)qrow0 * stride + base;
        const __half* Qr1 = Qr0 + (size_t)8 * stride;
        #pragma unroll
        for (int c = 0; c < 4; c++) {
            qf[c][0] = *(const unsigned*)(Qr0 + 16*c + 2*t);
            qf[c][1] = *(const unsigned*)(Qr1 + 16*c + 2*t);
            qf[c][2] = *(const unsigned*)(Qr0 + 16*c + 8 + 2*t);
            qf[c][3] = *(const unsigned*)(Qr1 + 16*c + 8 + 2*t);
        }
    }

    float oacc[8][4];
    #pragma unroll
    for (int n = 0; n < 8; n++)
        #pragma unroll
        for (int r = 0; r < 4; r++) oacc[n][r] = 0.f;
    float m0 = -1e30f, m1 = -1e30f, l0 = 0.f, l1 = 0.f;

    load_tile(0, 0);

    const int NT = SEQ / 64;
    for (int it = 0; it < NT; it++) {
        if (it + 1 < NT) {
            load_tile((it + 1) & 1, (it + 1) * 64);
            asm volatile("cp.async.wait_group 1;");
        } else {
            asm volatile("cp.async.wait_group 0;");
        }
        __syncthreads();
        const int s = it & 1;

        // ---- S = Q @ K^T ----
        float sacc[8][4];
        #pragma unroll
        for (int n = 0; n < 8; n++)
            #pragma unroll
            for (int r = 0; r < 4; r++) sacc[n][r] = 0.f;

        #pragma unroll
        for (int c = 0; c < 4; c++) {
            #pragma unroll
            for (int np = 0; np < 4; np++) {
                unsigned kf[4];
                ldsm_x4(kf, smem_u32(&Ks[s][np*16 + (lane & 7) + ((lane >> 4) << 3)]
                                        [c*8 + (((lane >> 3) & 1) << 2)]));
                mma_fp16(sacc[np*2],   qf[c][0], qf[c][1], qf[c][2], qf[c][3], kf[0], kf[1]);
                mma_fp16(sacc[np*2+1], qf[c][0], qf[c][1], qf[c][2], qf[c][3], kf[2], kf[3]);
            }
        }

        // ---- online softmax ----
        float mx0 = -1e30f, mx1 = -1e30f;
        #pragma unroll
        for (int n = 0; n < 8; n++) {
            sacc[n][0] *= 0.125f; sacc[n][1] *= 0.125f;
            sacc[n][2] *= 0.125f; sacc[n][3] *= 0.125f;
            mx0 = fmaxf(mx0, fmaxf(sacc[n][0], sacc[n][1]));
            mx1 = fmaxf(mx1, fmaxf(sacc[n][2], sacc[n][3]));
        }
        mx0 = fmaxf(mx0, __shfl_xor_sync(0xFFFFFFFFu, mx0, 1));
        mx0 = fmaxf(mx0, __shfl_xor_sync(0xFFFFFFFFu, mx0, 2));
        mx1 = fmaxf(mx1, __shfl_xor_sync(0xFFFFFFFFu, mx1, 1));
        mx1 = fmaxf(mx1, __shfl_xor_sync(0xFFFFFFFFu, mx1, 2));

        float nm0 = fmaxf(m0, mx0), nm1 = fmaxf(m1, mx1);
        float sc0 = __expf(m0 - nm0), sc1 = __expf(m1 - nm1);
        m0 = nm0; m1 = nm1;

        float rs0 = 0.f, rs1 = 0.f;
        unsigned pa[4][4];
        #pragma unroll
        for (int n = 0; n < 8; n++) {
            float p0 = __expf(sacc[n][0] - nm0);
            float p1 = __expf(sacc[n][1] - nm0);
            float p2 = __expf(sacc[n][2] - nm1);
            float p3 = __expf(sacc[n][3] - nm1);
            rs0 += p0 + p1; rs1 += p2 + p3;
            int kk = n >> 1, half = n & 1;
            pa[kk][half*2 + 0] = pack_half2(p0, p1);
            pa[kk][half*2 + 1] = pack_half2(p2, p3);
        }
        rs0 += __shfl_xor_sync(0xFFFFFFFFu, rs0, 1);
        rs0 += __shfl_xor_sync(0xFFFFFFFFu, rs0, 2);
        rs1 += __shfl_xor_sync(0xFFFFFFFFu, rs1, 1);
        rs1 += __shfl_xor_sync(0xFFFFFFFFu, rs1, 2);
        l0 = l0 * sc0 + rs0;
        l1 = l1 * sc1 + rs1;

        #pragma unroll
        for (int n = 0; n < 8; n++) {
            oacc[n][0] *= sc0; oacc[n][1] *= sc0;
            oacc[n][2] *= sc1; oacc[n][3] *= sc1;
        }

        // ---- O += P @ V (V frags via ldmatrix.trans) ----
        #pragma unroll
        for (int kk = 0; kk < 4; kk++) {
            #pragma unroll
            for (int nn = 0; nn < 8; nn += 2) {
                unsigned vf[4];
                ldsm_x4_t(vf, smem_u32(&Vs[s][kk*16 + (lane & 15)][(nn + (lane >> 4)) * 8]));
                mma_fp16(oacc[nn],   pa[kk][0], pa[kk][1], pa[kk][2], pa[kk][3], vf[0], vf[1]);
                mma_fp16(oacc[nn+1], pa[kk][0], pa[kk][1], pa[kk][2], pa[kk][3], vf[2], vf[3]);
            }
        }
        __syncthreads();
    }

    float inv0 = 1.f / l0, inv1 = 1.f / l1;
    __half* Or0 = O + (size_t)qrow0 * stride + base;
    __half* Or1 = Or0 + (size_t)8 * stride;
    #pragma unroll
    for (int nn = 0; nn < 8; nn++) {
        *(__half2*)(Or0 + nn*8 + 2*t) =
            __floats2half2_rn(oacc[nn][0] * inv0, oacc[nn][1] * inv0);
        *(__half2*)(Or1 + nn*8 + 2*t) =
            __floats2half2_rn(oacc[nn][2] * inv1, oacc[nn][3] * inv1);
    }
}

// ---------------- residual add + LN, fp16 B operand (LN1) -------------------
__global__ __launch_bounds__(256)
void add_ln_hB(const float* __restrict__ A, const __half* __restrict__ B,
               const float* __restrict__ g, const float* __restrict__ bta,
               float* __restrict__ out, __half* __restrict__ oh)
{
    const int row = blockIdx.x;
    const int tid = threadIdx.x;
    const float* a = A + (size_t)row * DM;
    const __half* b = B + (size_t)row * DM;

    float v[4];
    float4 va = *(const float4*)(a + tid * 4);
    __half2 hb0 = *(const __half2*)(b + tid * 4);
    __half2 hb1 = *(const __half2*)(b + tid * 4 + 2);
    float2 fb0 = __half22float2(hb0);
    float2 fb1 = __half22float2(hb1);
    v[0] = va.x + fb0.x; v[1] = va.y + fb0.y;
    v[2] = va.z + fb1.x; v[3] = va.w + fb1.y;

    float sum = v[0] + v[1] + v[2] + v[3];
    float sq  = v[0]*v[0] + v[1]*v[1] + v[2]*v[2] + v[3]*v[3];

    #pragma unroll
    for (int off = 16; off; off >>= 1) {
        sum += __shfl_xor_sync(0xFFFFFFFF, sum, off);
        sq  += __shfl_xor_sync(0xFFFFFFFF, sq,  off);
    }
    __shared__ float ssum[8], ssq[8], sstat[2];
    if ((tid & 31) == 0) { ssum[tid >> 5] = sum; ssq[tid >> 5] = sq; }
    __syncthreads();
    if (tid == 0) {
        float ts = 0.f, tq = 0.f;
        #pragma unroll
        for (int i = 0; i < 8; i++) { ts += ssum[i]; tq += ssq[i]; }
        float mean = ts / (float)DM;
        float var  = tq / (float)DM - mean * mean;
        sstat[0] = mean;
        sstat[1] = rsqrtf(fmaxf(var, 0.f) + LN_EPS);
    }
    __syncthreads();
    float mean = sstat[0], inv = sstat[1];

    float4 vg = *(const float4*)(g   + tid * 4);
    float4 vB = *(const float4*)(bta + tid * 4);
    float4 r;
    r.x = (v[0] - mean) * inv * vg.x + vB.x;
    r.y = (v[1] - mean) * inv * vg.y + vB.y;
    r.z = (v[2] - mean) * inv * vg.z + vB.z;
    r.w = (v[3] - mean) * inv * vg.w + vB.w;
    *(float4*)(out + (size_t)row * DM + tid * 4) = r;

    *(__half2*)(oh + (size_t)row * DM + tid * 4)     = __floats2half2_rn(r.x, r.y);
    *(__half2*)(oh + (size_t)row * DM + tid * 4 + 2) = __floats2half2_rn(r.z, r.w);
}

// ---------------- residual add + LN, fp32 B operand (LN2) -------------------
__global__ __launch_bounds__(256)
void add_ln_kernel(const float* __restrict__ A, const float* __restrict__ B,
                   const float* __restrict__ g, const float* __restrict__ bta,
                   float* __restrict__ out)
{
    const int row = blockIdx.x;
    const int tid = threadIdx.x;
    const float* a = A + (size_t)row * DM;
    const float* b = B + (size_t)row * DM;

    float v[4];
    float4 va = *(const float4*)(a + tid * 4);
    float4 vb = *(const float4*)(b + tid * 4);
    v[0] = va.x + vb.x; v[1] = va.y + vb.y;
    v[2] = va.z + vb.z; v[3] = va.w + vb.w;

    float sum = v[0] + v[1] + v[2] + v[3];
    float sq  = v[0]*v[0] + v[1]*v[1] + v[2]*v[2] + v[3]*v[3];

    #pragma unroll
    for (int off = 16; off; off >>= 1) {
        sum += __shfl_xor_sync(0xFFFFFFFF, sum, off);
        sq  += __shfl_xor_sync(0xFFFFFFFF, sq,  off);
    }
    __shared__ float ssum[8], ssq[8], sstat[2];
    if ((tid & 31) == 0) { ssum[tid >> 5] = sum; ssq[tid >> 5] = sq; }
    __syncthreads();
    if (tid == 0) {
        float ts = 0.f, tq = 0.f;
        #pragma unroll
        for (int i = 0; i < 8; i++) { ts += ssum[i]; tq += ssq[i]; }
        float mean = ts / (float)DM;
        float var  = tq / (float)DM - mean * mean;
        sstat[0] = mean;
        sstat[1] = rsqrtf(fmaxf(var, 0.f) + LN_EPS);
    }
    __syncthreads();
    float mean = sstat[0], inv = sstat[1];

    float4 vg = *(const float4*)(g   + tid * 4);
    float4 vB = *(const float4*)(bta + tid * 4);
    float4 r;
    r.x = (v[0] - mean) * inv * vg.x + vB.x;
    r.y = (v[1] - mean) * inv * vg.y + vB.y;
    r.z = (v[2] - mean) * inv * vg.z + vB.z;
    r.w = (v[3] - mean) * inv * vg.w + vB.w;
    *(float4*)(out + (size_t)row * DM + tid * 4) = r;
}

// ---------------------------------------------------------------------------
extern "C" void kernel_launch(void* const* d_in, const int* in_sizes, int n_in,
                              void* d_out, int out_size)
{
    const float* src  = (const float*)d_in[0];
    const float* q_w  = (const float*)d_in[1];
    const float* q_b  = (const float*)d_in[2];
    const float* k_w  = (const float*)d_in[3];
    const float* k_b  = (const float*)d_in[4];
    const float* v_w  = (const float*)d_in[5];
    const float* v_b  = (const float*)d_in[6];
    const float* w1   = (const float*)d_in[7];
    const float* b1   = (const float*)d_in[8];
    const float* w2   = (const float*)d_in[9];
    const float* b2   = (const float*)d_in[10];
    const float* ln1g = (const float*)d_in[11];
    const float* ln1b = (const float*)d_in[12];
    const float* ln2g = (const float*)d_in[13];
    const float* ln2b = (const float*)d_in[14];
    float* out = (float*)d_out;

    float *att, *x;
    float2* tbl;
    __half *sh, *xh, *ffh, *qh, *kh, *vh, *atth, *wqkvt, *w1t, *w2t;
    cudaGetSymbolAddress((void**)&att,   g_att);
    cudaGetSymbolAddress((void**)&x,     g_x);
    cudaGetSymbolAddress((void**)&sh,    g_srch);
    cudaGetSymbolAddress((void**)&xh,    g_xh);
    cudaGetSymbolAddress((void**)&ffh,   g_ffh);
    cudaGetSymbolAddress((void**)&qh,    g_qh);
    cudaGetSymbolAddress((void**)&kh,    g_kh);
    cudaGetSymbolAddress((void**)&vh,    g_vh);
    cudaGetSymbolAddress((void**)&atth,  g_atth);
    cudaGetSymbolAddress((void**)&wqkvt, g_wqkvt);
    cudaGetSymbolAddress((void**)&w1t,   g_w1t);
    cudaGetSymbolAddress((void**)&w2t,   g_w2t);
    cudaGetSymbolAddress((void**)&tbl,   g_rope);

    cudaFuncSetAttribute(gemm_qkv, cudaFuncAttributeMaxDynamicSharedMemorySize, GEMM_SMEM);
    cudaFuncSetAttribute(gemm_fp16<1,1>, cudaFuncAttributeMaxDynamicSharedMemorySize, GEMM_SMEM);
    cudaFuncSetAttribute(gemm_fp16<0,0>, cudaFuncAttributeMaxDynamicSharedMemorySize, GEMM_SMEM);

    // pre-pass (round-12 proven configuration)
    to_half<<<SB * DM / 4 / 256, 256>>>(src, sh, SB * DM / 4);
    dim3 tb(32, 8);
    transpose_qkv<<<dim3(DM / 32, DM / 32, 3), tb>>>(q_w, k_w, v_w, wqkvt);
    transpose_half<<<dim3(DFF / 32, DM / 32), tb>>>(w1, w1t, DM, DFF);
    transpose_half<<<dim3(DM / 32, DFF / 32), tb>>>(w2, w2t, DFF, DM);
    rope_table<<<SEQ * 32 / 256, 256>>>(tbl);

    // fused QKV (+bias +rope) -> fp16 q,k,v
    gemm_qkv<<<dim3(3 * DM / 128, SB / 128), 256, GEMM_SMEM>>>(
        sh, wqkvt, q_b, k_b, v_b, tbl, qh, kh, vh);

    attn_mma<<<dim3(SEQ / 128, NH, BATCH), 256>>>(qh, kh, vh, atth);
    add_ln_hB<<<SB, 256>>>(src, atth, ln1g, ln1b, x, xh);

    // FFN
    gemm_fp16<1,1><<<dim3(DFF / 128, SB / 128), 256, GEMM_SMEM>>>(
        xh, w1t, b1, nullptr, ffh, SB, DFF, DM);
    gemm_fp16<0,0><<<dim3(DM / 128, SB / 128), 256, GEMM_SMEM>>>(
        ffh, w2t, b2, att, nullptr, SB, DM, DFF);

    add_ln_kernel<<<SB, 256>>>(x, att, ln2g, ln2b, out);
}

// round 16
// speedup vs baseline: 1.5114x; 1.0085x over previous
#include <cuda_runtime.h>
#include <cuda_fp16.h>
#include <math.h>
#include <stdint.h>

#define SEQ    2048
#define BATCH  2
#define DM     1024
#define NH     16
#define HD     64
#define DFF    4096
#define SB     (SEQ*BATCH)          /* 4096 rows */
#define LN_EPS 1e-5f

// ---------------- scratch (static __device__, allocation-rule safe) ---------
__device__ float g_att[SB*DM];
__device__ float g_x [SB*DM];

__device__ __half g_srch[SB*DM];
__device__ __half g_xh  [SB*DM];
__device__ __half g_ffh [SB*DFF];
__device__ __half g_qh  [SB*DM];
__device__ __half g_kh  [SB*DM];
__device__ __half g_vh  [SB*DM];
__device__ __half g_atth[SB*DM];
__device__ __half g_wqkvt[3*DM*DM];   // [3072][1024] pre-transposed
__device__ __half g_w1t [DFF*DM];
__device__ __half g_w2t [DM*DFF];
__device__ float2 g_rope[SEQ*32];     // cos/sin per (s, pair)

// ---------------- helpers ---------------------------------------------------
__device__ __forceinline__ unsigned pack_half2(float lo, float hi) {
    __half2 h = __floats2half2_rn(lo, hi);
    return reinterpret_cast<unsigned&>(h);
}
__device__ __forceinline__ void cp16(unsigned dst, const void* gmem) {
    asm volatile("cp.async.cg.shared.global [%0], [%1], 16;" :: "r"(dst), "l"(gmem));
}
__device__ __forceinline__ unsigned smem_u32(const void* p) {
    return (unsigned)__cvta_generic_to_shared(p);
}
__device__ __forceinline__ void mma_fp16(float c[4],
                                         unsigned a0, unsigned a1, unsigned a2, unsigned a3,
                                         unsigned b0, unsigned b1) {
    asm volatile(
        "mma.sync.aligned.m16n8k16.row.col.f32.f16.f16.f32 "
        "{%0,%1,%2,%3}, {%4,%5,%6,%7}, {%8,%9}, {%0,%1,%2,%3};"
        : "+f"(c[0]), "+f"(c[1]), "+f"(c[2]), "+f"(c[3])
        : "r"(a0), "r"(a1), "r"(a2), "r"(a3), "r"(b0), "r"(b1));
}
__device__ __forceinline__ void ldsm_x4(unsigned r[4], unsigned addr) {
    asm volatile("ldmatrix.sync.aligned.m8n8.x4.shared.b16 {%0,%1,%2,%3}, [%4];"
                 : "=r"(r[0]), "=r"(r[1]), "=r"(r[2]), "=r"(r[3]) : "r"(addr));
}
__device__ __forceinline__ void ldsm_x4_t(unsigned r[4], unsigned addr) {
    asm volatile("ldmatrix.sync.aligned.m8n8.x4.trans.shared.b16 {%0,%1,%2,%3}, [%4];"
                 : "=r"(r[0]), "=r"(r[1]), "=r"(r[2]), "=r"(r[3]) : "r"(addr));
}

// ====== GEMM mainloop core (128x128 tile, BK=64, 2-stage, 128 thr, occ 2) ===
// 4 warps (2x2), warp tile 64x64. Dynamic smem: As/Bs [2][128][36] u32 (72 KB).
#define GEMM_SMEM (2 * 2 * 128 * 36 * 4)

#define GEMM_PROLOG(Aptr, Btptr, Kdim)                                           \
    extern __shared__ char dsm[];                                                \
    unsigned (*As)[128][36] = (unsigned(*)[128][36])dsm;                         \
    unsigned (*Bs)[128][36] = (unsigned(*)[128][36])(dsm + 2 * 128 * 36 * 4);    \
    const int tid  = threadIdx.x;                                                \
    const int warp = tid >> 5, lane = tid & 31;                                  \
    const int g = lane >> 2, t = lane & 3;                                       \
    const int wm = warp >> 1, wn = warp & 1;                                     \
    const int bm = blockIdx.y * 128, bn = blockIdx.x * 128;                      \
    float acc[4][8][4];                                                          \
    _Pragma("unroll") for (int i = 0; i < 4; i++)                                \
        _Pragma("unroll") for (int j = 0; j < 8; j++)                            \
            _Pragma("unroll") for (int r = 0; r < 4; r++) acc[i][j][r] = 0.f;    \
    const int NC = (Kdim) >> 6;                                                  \
    auto load_stage = [&](int s, int kt) {                                       \
        _Pragma("unroll")                                                        \
        for (int u = 0; u < 8; u++) {                                            \
            int f = tid + u * 128;                                               \
            int r = f >> 3, j = f & 7;                                           \
            cp16(smem_u32(&As[s][r][j * 4]), (Aptr)  + (size_t)(bm + r) * (Kdim) + kt + j * 8); \
            cp16(smem_u32(&Bs[s][r][j * 4]), (Btptr) + (size_t)(bn + r) * (Kdim) + kt + j * 8); \
        }                                                                        \
        asm volatile("cp.async.commit_group;");                                  \
    };                                                                           \
    load_stage(0, 0);                                                            \
    for (int c = 0; c < NC; c++) {                                               \
        if (c + 1 < NC) {                                                        \
            load_stage((c + 1) & 1, (c + 1) * 64);                               \
            asm volatile("cp.async.wait_group 1;");                              \
        } else {                                                                 \
            asm volatile("cp.async.wait_group 0;");                              \
        }                                                                        \
        __syncthreads();                                                         \
        const int s = c & 1;                                                     \
        _Pragma("unroll")                                                        \
        for (int ks = 0; ks < 4; ks++) {                                         \
            const int kp = ks * 8;                                               \
            unsigned a[4][4];                                                    \
            _Pragma("unroll")                                                    \
            for (int mf = 0; mf < 4; mf++) {                                     \
                int m = wm * 64 + mf * 16;                                       \
                ldsm_x4(a[mf], smem_u32(&As[s][m + (lane & 15)][kp + ((lane >> 4) << 2)])); \
            }                                                                    \
            _Pragma("unroll")                                                    \
            for (int np = 0; np < 4; np++) {                                     \
                int n = wn * 64 + np * 16;                                       \
                unsigned bf[4];                                                  \
                ldsm_x4(bf, smem_u32(&Bs[s][n + (lane & 7) + ((lane >> 4) << 3)][kp + (((lane >> 3) & 1) << 2)])); \
                _Pragma("unroll")                                                \
                for (int mf = 0; mf < 4; mf++) {                                 \
                    mma_fp16(acc[mf][np*2],   a[mf][0], a[mf][1], a[mf][2], a[mf][3], bf[0], bf[1]); \
                    mma_fp16(acc[mf][np*2+1], a[mf][0], a[mf][1], a[mf][2], a[mf][3], bf[2], bf[3]); \
                }                                                                \
            }                                                                    \
        }                                                                        \
        __syncthreads();                                                         \
    }

// ---------------- generic GEMM (FFN): C = A@Bt^T + bias ---------------------
template<int RELU, int HALF_OUT>
__global__ __launch_bounds__(128, 2)
void gemm_fp16(const __half* __restrict__ A, const __half* __restrict__ Bt,
               const float* __restrict__ bias,
               float* __restrict__ Cf, __half* __restrict__ Ch,
               int M, int N, int K)
{
    GEMM_PROLOG(A, Bt, K)

    #pragma unroll
    for (int mf = 0; mf < 4; mf++) {
        int r0 = bm + wm * 64 + mf * 16 + g;
        #pragma unroll
        for (int nf = 0; nf < 8; nf++) {
            int col = bn + wn * 64 + nf * 8 + 2 * t;
            float2 bv = *(const float2*)(bias + col);
            float v0 = acc[mf][nf][0] + bv.x;
            float v1 = acc[mf][nf][1] + bv.y;
            float v2 = acc[mf][nf][2] + bv.x;
            float v3 = acc[mf][nf][3] + bv.y;
            if (RELU) {
                v0 = fmaxf(v0, 0.f); v1 = fmaxf(v1, 0.f);
                v2 = fmaxf(v2, 0.f); v3 = fmaxf(v3, 0.f);
            }
            if (HALF_OUT) {
                *(__half2*)(Ch + (size_t)r0       * N + col) = __floats2half2_rn(v0, v1);
                *(__half2*)(Ch + (size_t)(r0 + 8) * N + col) = __floats2half2_rn(v2, v3);
            } else {
                *(float2*)(Cf + (size_t)r0       * N + col) = make_float2(v0, v1);
                *(float2*)(Cf + (size_t)(r0 + 8) * N + col) = make_float2(v2, v3);
            }
        }
    }
}

// ---------------- fused QKV GEMM: rope(q,k) + fp16 stores -------------------
__global__ __launch_bounds__(128, 2)
void gemm_qkv(const __half* __restrict__ A, const __half* __restrict__ Bt,
              const float* __restrict__ q_b, const float* __restrict__ k_b,
              const float* __restrict__ v_b,
              const float2* __restrict__ tbl,
              __half* __restrict__ Qh, __half* __restrict__ Kh,
              __half* __restrict__ Vh)
{
    GEMM_PROLOG(A, Bt, DM)

    const int sec   = blockIdx.x >> 3;          // 0=q 1=k 2=v (8 blocks each)
    const int ncol0 = bn & 1023;
    const float* bias = sec == 0 ? q_b : (sec == 1 ? k_b : v_b);
    __half* outp      = sec == 0 ? Qh  : (sec == 1 ? Kh  : Vh);
    const bool dorope = sec < 2;

    #pragma unroll
    for (int mf = 0; mf < 4; mf++) {
        int r0 = bm + wm * 64 + mf * 16 + g;
        int s0 = r0 >> 1, s1 = (r0 + 8) >> 1;     // BATCH=2: seq pos
        #pragma unroll
        for (int nf = 0; nf < 8; nf++) {
            int col = ncol0 + wn * 64 + nf * 8 + 2 * t;
            float2 bv = *(const float2*)(bias + col);
            float v0 = acc[mf][nf][0] + bv.x;
            float v1 = acc[mf][nf][1] + bv.y;
            float v2 = acc[mf][nf][2] + bv.x;
            float v3 = acc[mf][nf][3] + bv.y;
            if (dorope) {
                int p = (col & 63) >> 1;
                float2 cs0 = tbl[s0 * 32 + p];
                float2 cs1 = tbl[s1 * 32 + p];
                float t0 = v0 * cs0.x - v1 * cs0.y;
                v1 = v1 * cs0.x + v0 * cs0.y; v0 = t0;
                float t2 = v2 * cs1.x - v3 * cs1.y;
                v3 = v3 * cs1.x + v2 * cs1.y; v2 = t2;
            }
            *(__half2*)(outp + (size_t)r0       * DM + col) = __floats2half2_rn(v0, v1);
            *(__half2*)(outp + (size_t)(r0 + 8) * DM + col) = __floats2half2_rn(v2, v3);
        }
    }
}

// ---------------- pre-pass kernels (round-12 proven set) --------------------
__global__ void to_half(const float* __restrict__ X, __half* __restrict__ H, int n4)
{
    int i = blockIdx.x * blockDim.x + threadIdx.x;
    if (i >= n4) return;
    float4 v = *(const float4*)(X + i * 4);
    *(__half2*)(H + i * 4)     = __floats2half2_rn(v.x, v.y);
    *(__half2*)(H + i * 4 + 2) = __floats2half2_rn(v.z, v.w);
}

__global__ void transpose_half(const float* __restrict__ W, __half* __restrict__ T,
                               int K, int N)
{
    __shared__ float tl[32][33];
    int n0 = blockIdx.x * 32, k0 = blockIdx.y * 32;
    int x = threadIdx.x, y = threadIdx.y;
    #pragma unroll
    for (int i = 0; i < 4; i++) {
        int r = y + i * 8;
        tl[r][x] = W[(size_t)(k0 + r) * N + n0 + x];
    }
    __syncthreads();
    #pragma unroll
    for (int i = 0; i < 4; i++) {
        int r = y + i * 8;
        T[(size_t)(n0 + r) * K + k0 + x] = __float2half_rn(tl[x][r]);
    }
}

// all three QKV weights in one launch (z selects the weight)
__global__ void transpose_qkv(const float* __restrict__ Wq, const float* __restrict__ Wk,
                              const float* __restrict__ Wv, __half* __restrict__ T)
{
    __shared__ float tl[32][33];
    const float* W = blockIdx.z == 0 ? Wq : (blockIdx.z == 1 ? Wk : Wv);
    __half* Tz = T + (size_t)blockIdx.z * DM * DM;
    int n0 = blockIdx.x * 32, k0 = blockIdx.y * 32;
    int x = threadIdx.x, y = threadIdx.y;
    #pragma unroll
    for (int i = 0; i < 4; i++) {
        int r = y + i * 8;
        tl[r][x] = W[(size_t)(k0 + r) * DM + n0 + x];
    }
    __syncthreads();
    #pragma unroll
    for (int i = 0; i < 4; i++) {
        int r = y + i * 8;
        Tz[(size_t)(n0 + r) * DM + k0 + x] = __float2half_rn(tl[x][r]);
    }
}

__global__ void rope_table(float2* __restrict__ tbl)
{
    int i = blockIdx.x * blockDim.x + threadIdx.x;
    if (i >= SEQ * 32) return;
    int s = i >> 5, p = i & 31;
    float ang = (float)s * powf(10000.0f, -(float)p / 32.0f);
    tbl[i] = make_float2(cosf(ang), sinf(ang));
}

// ---------------- tensor-core flash attention (cp.async dbl-buf, fp16 out) --
// Grid (SEQ/128, NH, BATCH), 256 thr = 8 warps, warp owns 16 q-rows.
__global__ __launch_bounds__(256)
void attn_mma(const __half* __restrict__ Q, const __half* __restrict__ K,
              const __half* __restrict__ V, __half* __restrict__ O)
{
    const int qt = blockIdx.x, h = blockIdx.y, b = blockIdx.z;
    const int stride = BATCH * DM;
    const size_t base = (size_t)b * DM + h * HD;
    const int tid = threadIdx.x;
    const int w = tid >> 5, lane = tid & 31;
    const int g = lane >> 2, t = lane & 3;
    const int qrow0 = qt * 128 + w * 16 + g;

    __shared__ unsigned Ks[2][64][36];   // u32 view of fp16 [64][72-pad]
    __shared__ __half   Vs[2][64][72];   // fp16 rows (64 data + 8 pad)

    auto load_tile = [&](int s, int kt) {
        const __half* Kg = K + (size_t)kt * stride + base;
        const __half* Vg = V + (size_t)kt * stride + base;
        #pragma unroll
        for (int u = 0; u < 2; u++) {
            int i = tid + u * 256;
            int r = i >> 3, j = i & 7;
            cp16(smem_u32(&Ks[s][r][j * 4]), Kg + (size_t)r * stride + j * 8);
            cp16(smem_u32(&Vs[s][r][j * 8]), Vg + (size_t)r * stride + j * 8);
        }
        asm volatile("cp.async.commit_group;");
    };

    // Q fragments straight from fp16 gmem
    unsigned qf[4][4];
    {
        const __half* Qr0 = Q + (size_t)qrow0 * stride + base;
        const __half* Qr1 = Qr0 + (size_t)8 * stride;
        #pragma unroll
        for (int c = 0; c < 4; c++) {
            qf[c][0] = *(const unsigned*)(Qr0 + 16*c + 2*t);
            qf[c][1] = *(const unsigned*)(Qr1 + 16*c + 2*t);
            qf[c][2] = *(const unsigned*)(Qr0 + 16*c + 8 + 2*t);
            qf[c][3] = *(const unsigned*)(Qr1 + 16*c + 8 + 2*t);
        }
    }

    float oacc[8][4];
    #pragma unroll
    for (int n = 0; n < 8; n++)
        #pragma unroll
        for (int r = 0; r < 4; r++) oacc[n][r] = 0.f;
    float m0 = -1e30f, m1 = -1e30f, l0 = 0.f, l1 = 0.f;

    load_tile(0, 0);

    const int NT = SEQ / 64;
    for (int it = 0; it < NT; it++) {
        if (it + 1 < NT) {
            load_tile((it + 1) & 1, (it + 1) * 64);
            asm volatile("cp.async.wait_group 1;");
        } else {
            asm volatile("cp.async.wait_group 0;");
        }
        __syncthreads();
        const int s = it & 1;

        // ---- S = Q @ K^T ----
        float sacc[8][4];
        #pragma unroll
        for (int n = 0; n < 8; n++)
            #pragma unroll
            for (int r = 0; r < 4; r++) sacc[n][r] = 0.f;

        #pragma unroll
        for (int c = 0; c < 4; c++) {
            #pragma unroll
            for (int np = 0; np < 4; np++) {
                unsigned kf[4];
                ldsm_x4(kf, smem_u32(&Ks[s][np*16 + (lane & 7) + ((lane >> 4) << 3)]
                                        [c*8 + (((lane >> 3) & 1) << 2)]));
                mma_fp16(sacc[np*2],   qf[c][0], qf[c][1], qf[c][2], qf[c][3], kf[0], kf[1]);
                mma_fp16(sacc[np*2+1], qf[c][0], qf[c][1], qf[c][2], qf[c][3], kf[2], kf[3]);
            }
        }

        // ---- online softmax ----
        float mx0 = -1e30f, mx1 = -1e30f;
        #pragma unroll
        for (int n = 0; n < 8; n++) {
            sacc[n][0] *= 0.125f; sacc[n][1] *= 0.125f;
            sacc[n][2] *= 0.125f; sacc[n][3] *= 0.125f;
            mx0 = fmaxf(mx0, fmaxf(sacc[n][0], sacc[n][1]));
            mx1 = fmaxf(mx1, fmaxf(sacc[n][2], sacc[n][3]));
        }
        mx0 = fmaxf(mx0, __shfl_xor_sync(0xFFFFFFFFu, mx0, 1));
        mx0 = fmaxf(mx0, __shfl_xor_sync(0xFFFFFFFFu, mx0, 2));
        mx1 = fmaxf(mx1, __shfl_xor_sync(0xFFFFFFFFu, mx1, 1));
        mx1 = fmaxf(mx1, __shfl_xor_sync(0xFFFFFFFFu, mx1, 2));

        float nm0 = fmaxf(m0, mx0), nm1 = fmaxf(m1, mx1);
        float sc0 = __expf(m0 - nm0), sc1 = __expf(m1 - nm1);
        m0 = nm0; m1 = nm1;

        float rs0 = 0.f, rs1 = 0.f;
        unsigned pa[4][4];
        #pragma unroll
        for (int n = 0; n < 8; n++) {
            float p0 = __expf(sacc[n][0] - nm0);
            float p1 = __expf(sacc[n][1] - nm0);
            float p2 = __expf(sacc[n][2] - nm1);
            float p3 = __expf(sacc[n][3] - nm1);
            rs0 += p0 + p1; rs1 += p2 + p3;
            int kk = n >> 1, half = n & 1;
            pa[kk][half*2 + 0] = pack_half2(p0, p1);
            pa[kk][half*2 + 1] = pack_half2(p2, p3);
        }
        rs0 += __shfl_xor_sync(0xFFFFFFFFu, rs0, 1);
        rs0 += __shfl_xor_sync(0xFFFFFFFFu, rs0, 2);
        rs1 += __shfl_xor_sync(0xFFFFFFFFu, rs1, 1);
        rs1 += __shfl_xor_sync(0xFFFFFFFFu, rs1, 2);
        l0 = l0 * sc0 + rs0;
        l1 = l1 * sc1 + rs1;

        #pragma unroll
        for (int n = 0; n < 8; n++) {
            oacc[n][0] *= sc0; oacc[n][1] *= sc0;
            oacc[n][2] *= sc1; oacc[n][3] *= sc1;
        }

        // ---- O += P @ V (V frags via ldmatrix.trans) ----
        #pragma unroll
        for (int kk = 0; kk < 4; kk++) {
            #pragma unroll
            for (int nn = 0; nn < 8; nn += 2) {
                unsigned vf[4];
                ldsm_x4_t(vf, smem_u32(&Vs[s][kk*16 + (lane & 15)][(nn + (lane >> 4)) * 8]));
                mma_fp16(oacc[nn],   pa[kk][0], pa[kk][1], pa[kk][2], pa[kk][3], vf[0], vf[1]);
                mma_fp16(oacc[nn+1], pa[kk][0], pa[kk][1], pa[kk][2], pa[kk][3], vf[2], vf[3]);
            }
        }
        __syncthreads();
    }

    float inv0 = 1.f / l0, inv1 = 1.f / l1;
    __half* Or0 = O + (size_t)qrow0 * stride + base;
    __half* Or1 = Or0 + (size_t)8 * stride;
    #pragma unroll
    for (int nn = 0; nn < 8; nn++) {
        *(__half2*)(Or0 + nn*8 + 2*t) =
            __floats2half2_rn(oacc[nn][0] * inv0, oacc[nn][1] * inv0);
        *(__half2*)(Or1 + nn*8 + 2*t) =
            __floats2half2_rn(oacc[nn][2] * inv1, oacc[nn][3] * inv1);
    }
}

// ---------------- residual add + LN, fp16 B operand (LN1) -------------------
__global__ __launch_bounds__(256)
void add_ln_hB(const float* __restrict__ A, const __half* __restrict__ B,
               const float* __restrict__ g, const float* __restrict__ bta,
               float* __restrict__ out, __half* __restrict__ oh)
{
    const int row = blockIdx.x;
    const int tid = threadIdx.x;
    const float* a = A + (size_t)row * DM;
    const __half* b = B + (size_t)row * DM;

    float v[4];
    float4 va = *(const float4*)(a + tid * 4);
    __half2 hb0 = *(const __half2*)(b + tid * 4);
    __half2 hb1 = *(const __half2*)(b + tid * 4 + 2);
    float2 fb0 = __half22float2(hb0);
    float2 fb1 = __half22float2(hb1);
    v[0] = va.x + fb0.x; v[1] = va.y + fb0.y;
    v[2] = va.z + fb1.x; v[3] = va.w + fb1.y;

    float sum = v[0] + v[1] + v[2] + v[3];
    float sq  = v[0]*v[0] + v[1]*v[1] + v[2]*v[2] + v[3]*v[3];

    #pragma unroll
    for (int off = 16; off; off >>= 1) {
        sum += __shfl_xor_sync(0xFFFFFFFF, sum, off);
        sq  += __shfl_xor_sync(0xFFFFFFFF, sq,  off);
    }
    __shared__ float ssum[8], ssq[8], sstat[2];
    if ((tid & 31) == 0) { ssum[tid >> 5] = sum; ssq[tid >> 5] = sq; }
    __syncthreads();
    if (tid == 0) {
        float ts = 0.f, tq = 0.f;
        #pragma unroll
        for (int i = 0; i < 8; i++) { ts += ssum[i]; tq += ssq[i]; }
        float mean = ts / (float)DM;
        float var  = tq / (float)DM - mean * mean;
        sstat[0] = mean;
        sstat[1] = rsqrtf(fmaxf(var, 0.f) + LN_EPS);
    }
    __syncthreads();
    float mean = sstat[0], inv = sstat[1];

    float4 vg = *(const float4*)(g   + tid * 4);
    float4 vB = *(const float4*)(bta + tid * 4);
    float4 r;
    r.x = (v[0] - mean) * inv * vg.x + vB.x;
    r.y = (v[1] - mean) * inv * vg.y + vB.y;
    r.z = (v[2] - mean) * inv * vg.z + vB.z;
    r.w = (v[3] - mean) * inv * vg.w + vB.w;
    *(float4*)(out + (size_t)row * DM + tid * 4) = r;

    *(__half2*)(oh + (size_t)row * DM + tid * 4)     = __floats2half2_rn(r.x, r.y);
    *(__half2*)(oh + (size_t)row * DM + tid * 4 + 2) = __floats2half2_rn(r.z, r.w);
}

// ---------------- residual add + LN, fp32 B operand (LN2) -------------------
__global__ __launch_bounds__(256)
void add_ln_kernel(const float* __restrict__ A, const float* __restrict__ B,
                   const float* __restrict__ g, const float* __restrict__ bta,
                   float* __restrict__ out)
{
    const int row = blockIdx.x;
    const int tid = threadIdx.x;
    const float* a = A + (size_t)row * DM;
    const float* b = B + (size_t)row * DM;

    float v[4];
    float4 va = *(const float4*)(a + tid * 4);
    float4 vb = *(const float4*)(b + tid * 4);
    v[0] = va.x + vb.x; v[1] = va.y + vb.y;
    v[2] = va.z + vb.z; v[3] = va.w + vb.w;

    float sum = v[0] + v[1] + v[2] + v[3];
    float sq  = v[0]*v[0] + v[1]*v[1] + v[2]*v[2] + v[3]*v[3];

    #pragma unroll
    for (int off = 16; off; off >>= 1) {
        sum += __shfl_xor_sync(0xFFFFFFFF, sum, off);
        sq  += __shfl_xor_sync(0xFFFFFFFF, sq,  off);
    }
    __shared__ float ssum[8], ssq[8], sstat[2];
    if ((tid & 31) == 0) { ssum[tid >> 5] = sum; ssq[tid >> 5] = sq; }
    __syncthreads();
    if (tid == 0) {
        float ts = 0.f, tq = 0.f;
        #pragma unroll
        for (int i = 0; i < 8; i++) { ts += ssum[i]; tq += ssq[i]; }
        float mean = ts / (float)DM;
        float var  = tq / (float)DM - mean * mean;
        sstat[0] = mean;
        sstat[1] = rsqrtf(fmaxf(var, 0.f) + LN_EPS);
    }
    __syncthreads();
    float mean = sstat[0], inv = sstat[1];

    float4 vg = *(const float4*)(g   + tid * 4);
    float4 vB = *(const float4*)(bta + tid * 4);
    float4 r;
    r.x = (v[0] - mean) * inv * vg.x + vB.x;
    r.y = (v[1] - mean) * inv * vg.y + vB.y;
    r.z = (v[2] - mean) * inv * vg.z + vB.z;
    r.w = (v[3] - mean) * inv * vg.w + vB.w;
    *(float4*)(out + (size_t)row * DM + tid * 4) = r;
}

// ---------------------------------------------------------------------------
extern "C" void kernel_launch(void* const* d_in, const int* in_sizes, int n_in,
                              void* d_out, int out_size)
{
    const float* src  = (const float*)d_in[0];
    const float* q_w  = (const float*)d_in[1];
    const float* q_b  = (const float*)d_in[2];
    const float* k_w  = (const float*)d_in[3];
    const float* k_b  = (const float*)d_in[4];
    const float* v_w  = (const float*)d_in[5];
    const float* v_b  = (const float*)d_in[6];
    const float* w1   = (const float*)d_in[7];
    const float* b1   = (const float*)d_in[8];
    const float* w2   = (const float*)d_in[9];
    const float* b2   = (const float*)d_in[10];
    const float* ln1g = (const float*)d_in[11];
    const float* ln1b = (const float*)d_in[12];
    const float* ln2g = (const float*)d_in[13];
    const float* ln2b = (const float*)d_in[14];
    float* out = (float*)d_out;

    float *att, *x;
    float2* tbl;
    __half *sh, *xh, *ffh, *qh, *kh, *vh, *atth, *wqkvt, *w1t, *w2t;
    cudaGetSymbolAddress((void**)&att,   g_att);
    cudaGetSymbolAddress((void**)&x,     g_x);
    cudaGetSymbolAddress((void**)&sh,    g_srch);
    cudaGetSymbolAddress((void**)&xh,    g_xh);
    cudaGetSymbolAddress((void**)&ffh,   g_ffh);
    cudaGetSymbolAddress((void**)&qh,    g_qh);
    cudaGetSymbolAddress((void**)&kh,    g_kh);
    cudaGetSymbolAddress((void**)&vh,    g_vh);
    cudaGetSymbolAddress((void**)&atth,  g_atth);
    cudaGetSymbolAddress((void**)&wqkvt, g_wqkvt);
    cudaGetSymbolAddress((void**)&w1t,   g_w1t);
    cudaGetSymbolAddress((void**)&w2t,   g_w2t);
    cudaGetSymbolAddress((void**)&tbl,   g_rope);

    cudaFuncSetAttribute(gemm_qkv, cudaFuncAttributeMaxDynamicSharedMemorySize, GEMM_SMEM);
    cudaFuncSetAttribute(gemm_fp16<1,1>, cudaFuncAttributeMaxDynamicSharedMemorySize, GEMM_SMEM);
    cudaFuncSetAttribute(gemm_fp16<0,0>, cudaFuncAttributeMaxDynamicSharedMemorySize, GEMM_SMEM);

    // pre-pass (round-12 proven configuration)
    to_half<<<SB * DM / 4 / 256, 256>>>(src, sh, SB * DM / 4);
    dim3 tb(32, 8);
    transpose_qkv<<<dim3(DM / 32, DM / 32, 3), tb>>>(q_w, k_w, v_w, wqkvt);
    transpose_half<<<dim3(DFF / 32, DM / 32), tb>>>(w1, w1t, DM, DFF);
    transpose_half<<<dim3(DM / 32, DFF / 32), tb>>>(w2, w2t, DFF, DM);
    rope_table<<<SEQ * 32 / 256, 256>>>(tbl);

    // fused QKV (+bias +rope) -> fp16 q,k,v
    gemm_qkv<<<dim3(3 * DM / 128, SB / 128), 128, GEMM_SMEM>>>(
        sh, wqkvt, q_b, k_b, v_b, tbl, qh, kh, vh);

    attn_mma<<<dim3(SEQ / 128, NH, BATCH), 256>>>(qh, kh, vh, atth);
    add_ln_hB<<<SB, 256>>>(src, atth, ln1g, ln1b, x, xh);

    // FFN
    gemm_fp16<1,1><<<dim3(DFF / 128, SB / 128), 128, GEMM_SMEM>>>(
        xh, w1t, b1, nullptr, ffh, SB, DFF, DM);
    gemm_fp16<0,0><<<dim3(DM / 128, SB / 128), 128, GEMM_SMEM>>>(
        ffh, w2t, b2, att, nullptr, SB, DM, DFF);

    add_ln_kernel<<<SB, 256>>>(x, att, ln2g, ln2b, out);
}